// round 6
// baseline (speedup 1.0000x reference)
#include <cuda_runtime.h>
#include <cuda_bf16.h>
#include <cstdint>

// OTAM cumulative soft-min DP.  dists: [200,200,32,32] f32 -> out [200,200] f32.
// lambda = 0.5.  Scaled space: W = v * C2 with C2 = 1/(lambda*ln2), so
//   softmin step:  Wv = dm*C2 + Wtm - log2(sum 2^(Wtm - Wx))
// (the lambda*ln2 factor cancels).  Final output = W * lambda*ln2.
//
// Round-6: K=6 skewed rows in flight per thread (strips 3,6,6,6,6,4 over
// rows 1..31) to saturate MUFU; per-warp cp.async staging of 6-row chunks
// (stride 49 float4 -> conflict-free); 64-thread blocks, 625 blocks,
// 50.2KB smem -> ~4 blocks/SM resident, ~8.4 warps/SM.

#define QTOT 40000
#define PPW 32                  // problems per warp
#define PPB 64                  // threads per block (2 warps)
#define CHUNK_WORDS 196         // 6 rows * 32 floats + 4 pad (784B)
#define BUF_WORDS (PPB * CHUNK_WORDS)   // 12544 floats = 50176 B

__device__ __forceinline__ float ex2f(float x) {
    float y; asm("ex2.approx.f32 %0, %1;" : "=f"(y) : "f"(x)); return y;
}
__device__ __forceinline__ float lg2f(float x) {
    float y; asm("lg2.approx.f32 %0, %1;" : "=f"(y) : "f"(x)); return y;
}
__device__ __forceinline__ void cp_async16(unsigned int dst, const void* src) {
    asm volatile("cp.async.cg.shared.global [%0], [%1], 16;\n"
                 :: "r"(dst), "l"(src) : "memory");
}

// constant-index access into a float4 (folds at compile time)
#define ELT4(v, k) ((k)==0 ? (v).x : ((k)==1 ? (v).y : ((k)==2 ? (v).z : (v).w)))

// K skewed rows in flight (row r one column ahead of row r+1).
// rows[r*32 + j] = d(row r, col j) in this thread's smem chunk.
// prev[0..33] (W-scaled): completed row above the strip on entry, bottom row
// on exit.  Hazard: bottom row writes prev[m] at step m+K-1; row 0 last reads
// prev[m] at step m+1 -> K>=3 required.
template<int K>
__device__ __forceinline__ void run_strip(const float* __restrict__ rows, float* prev) {
    const float C2 = 2.8853900817779268f;   // 1/(lambda*ln2)

    float cum[K], cumP[K];
    #pragma unroll
    for (int r = 0; r < K; r++) { cum[r] = 0.0f; cumP[r] = 0.0f; }

    float4 d4[K];

    #pragma unroll
    for (int t = 1; t <= 33 + K - 1; t++) {
        #pragma unroll
        for (int r = K - 1; r >= 0; r--) {
            const int m = t - r;
            if (m >= 1 && m <= 33) {
                const int j = m - 1;
                if (j < 32 && (j & 3) == 0)
                    d4[r] = *reinterpret_cast<const float4*>(rows + r * 32 + j);
                const float dmC2 = (j < 32) ? ELT4(d4[r], j & 3) * C2 : 0.0f; // off-chain
                const float a  = (r == 0) ? prev[m - 1] : cumP[r - 1];  // diag (W)
                const float c  = cum[r];                                // left (W)
                float v;
                if (m == 1 || m == 33) {
                    const float pm = (r == 0) ? prev[m] : cum[r - 1];   // above (W)
                    float tm = fminf(fminf(a, c), pm);
                    float s  = ex2f(tm - a) + ex2f(tm - c) + ex2f(tm - pm);
                    v = (dmC2 + tm) - lg2f(s);
                } else {
                    float tm = fminf(a, c);
                    float u  = fmaxf(a, c);
                    float s  = 1.0f + ex2f(tm - u);
                    v = (dmC2 + tm) - lg2f(s);
                }
                cumP[r] = cum[r];
                cum[r]  = v;
                if (r == K - 1) prev[m] = v;
            }
        }
    }
}

__global__ void __launch_bounds__(PPB)
otam_kernel(const float* __restrict__ dists, float* __restrict__ out) {
    extern __shared__ float smem[];          // BUF_WORDS floats
    const float C2   = 2.8853900817779268f;  // 1/(lambda*ln2)
    const float LLN2 = 0.34657359027997264f; // lambda*ln2

    const int lane = threadIdx.x & 31;
    const int wid  = threadIdx.x >> 5;
    const int pw   = blockIdx.x * PPB + wid * PPW;   // 625*64 == 40000 exactly

    float* wsm = smem + wid * (PPW * CHUNK_WORDS);   // this warp's region
    const unsigned int wsm_u32 = (unsigned int)__cvta_generic_to_shared(wsm);

    // Stage loader: R rows (R*8 float4 per problem) for this warp's 32
    // problems, coalesced 16B cp.asyncs.  R <= 6.
    auto prefetch = [&](int row_base, int R) {
        const int nf4 = R * 8;
        #pragma unroll
        for (int i = 0; i < PPW; i++) {
            #pragma unroll
            for (int j = 0; j < 2; j++) {       // up to 64 f4 per chunk
                const int c = j * 32 + lane;
                if (c < nf4) {
                    const float* g = dists + (size_t)(pw + i) * 1024
                                   + row_base * 32 + c * 4;
                    const unsigned int s = wsm_u32
                        + (unsigned int)(i * CHUNK_WORDS + c * 4) * 4u;
                    cp_async16(s, g);
                }
            }
        }
        asm volatile("cp.async.commit_group;\n" ::);
    };

    float prev[34];
    const float* ch = wsm + lane * CHUNK_WORDS;      // this thread's chunk

    // ---- stage 0: rows 0..3
    prefetch(0, 4);
    asm volatile("cp.async.wait_group 0;\n" ::);
    __syncwarp();
    {
        // row 0: W-scaled cumulative sum of padded row
        float4 r0[8];
        #pragma unroll
        for (int i = 0; i < 8; i++)
            r0[i] = *reinterpret_cast<const float4*>(ch + 4 * i);
        prev[0] = 0.0f;
        #pragma unroll
        for (int m = 1; m <= 32; m++) {
            const int j = m - 1;
            prev[m] = prev[m - 1] + ELT4(r0[j >> 2], j & 3) * C2;
        }
        prev[33] = prev[32];    // padded d = 0
    }
    run_strip<3>(ch + 32, prev);        // rows 1..3

    // ---- stages 1..4: rows 4..27, K=6
    #pragma unroll 1
    for (int s = 0; s < 4; s++) {
        __syncwarp();                   // all lanes done with previous stage
        prefetch(4 + 6 * s, 6);
        asm volatile("cp.async.wait_group 0;\n" ::);
        __syncwarp();
        run_strip<6>(ch, prev);
    }

    // ---- stage 5: rows 28..31, K=4
    __syncwarp();
    prefetch(28, 4);
    asm volatile("cp.async.wait_group 0;\n" ::);
    __syncwarp();
    run_strip<4>(ch, prev);

    out[pw + lane] = prev[33] * LLN2;   // unscale
}

extern "C" void kernel_launch(void* const* d_in, const int* in_sizes, int n_in,
                              void* d_out, int out_size) {
    const float* dists = (const float*)d_in[0];
    float* out = (float*)d_out;
    const int blocks = QTOT / PPB;                    // 625
    const size_t shmem = BUF_WORDS * sizeof(float);   // 50176 B
    cudaFuncSetAttribute(otam_kernel, cudaFuncAttributeMaxDynamicSharedMemorySize,
                         (int)shmem);
    otam_kernel<<<blocks, PPB, shmem>>>(dists, out);
}

// round 8
// speedup vs baseline: 1.2454x; 1.2454x over previous
#include <cuda_runtime.h>
#include <cuda_bf16.h>
#include <cstdint>

// OTAM cumulative soft-min DP.  dists: [200,200,32,32] f32 -> out [200,200] f32.
// lambda = 0.5.
//
// Round-7: EXPONENTIAL-DOMAIN recurrence. Track E(l,m) = 2^(S - v(l,m)*C2),
// C2 = 1/(lambda*ln2), fixed scale S = 96. Then:
//   interior:  E[m] = w_m * (E[m-1] + P[m-1])      (P = prev row's E)
//   m==1:      E[1] = w_1 * (2^(S+1) + P[1])       (two zero-terms 2^S + above)
//   m==33:     E[33] = E[32] + P[32] + P[33]       (d=0 -> w=1)
//   row 0:     E[m] = E[m-1] * w_m,  E[33]=E[32]
//   w_m = 2^(-d_m*C2)  (EX2, off the dependent chain)
//   out = lambda*ln2 * (S - log2(E(31,33)))
// Dependent chain per cell = ONE FFMA (4 cyc) instead of min->EX2->LG2 (~50).
// Range: d in [0,2] => v in [-1, 84] => exponents in [-146, 101]: safe in f32.
//
// Memory: per-warp double-buffered 2-row cp.async stages (16 stages/problem),
// prefetch stage s+2 into the buffer freed by stage s -> DRAM-bound streaming.

#define QTOT 40000
#define PPW 32                    // problems per warp
#define PPB 128                   // threads per block (4 warps)
#define CHUNK_WORDS 68            // 64 data floats (2 rows) + 4 pad
#define BUF_WORDS_1 (PPW * CHUNK_WORDS)      // one buffer per warp: 2176 floats
#define WARP_WORDS (2 * BUF_WORDS_1)         // double buffered: 4352 floats
#define SMEM_WORDS (4 * WARP_WORDS)          // 17408 floats = 69632 B / block

__device__ __forceinline__ float ex2f(float x) {
    float y; asm("ex2.approx.f32 %0, %1;" : "=f"(y) : "f"(x)); return y;
}
__device__ __forceinline__ float lg2f(float x) {
    float y; asm("lg2.approx.f32 %0, %1;" : "=f"(y) : "f"(x)); return y;
}
__device__ __forceinline__ void cp_async16(unsigned int dst, const void* src) {
    asm volatile("cp.async.cg.shared.global [%0], [%1], 16;\n"
                 :: "r"(dst), "l"(src) : "memory");
}

#define ELT4(v, k) ((k)==0 ? (v).x : ((k)==1 ? (v).y : ((k)==2 ? (v).z : (v).w)))

#define NC2    (-2.8853900817779268f)   // -1/(lambda*ln2)
#define LLN2   (0.34657359027997264f)   // lambda*ln2
#define TWO_S  (7.922816251426434e28f)  // 2^96
#define TWO_S2 (1.5845632502852868e29f) // 2^97
#define SLLN2  (33.271064666877374f)    // 96 * lambda*ln2

// General row (l >= 1): read prev-row E in P[1..33], write this row into N[1..33].
// drow: this row's 32 d-values in this thread's smem chunk.
__device__ __forceinline__ void row_step(const float* __restrict__ drow,
                                         const float* __restrict__ P,
                                         float* __restrict__ N) {
    float4 dq = *reinterpret_cast<const float4*>(drow);
    float w = ex2f(dq.x * NC2);
    N[1] = w * (TWO_S2 + P[1]);
    #pragma unroll
    for (int m = 2; m <= 32; m++) {
        const int j = m - 1;
        if ((j & 3) == 0) dq = *reinterpret_cast<const float4*>(drow + j);
        w = ex2f(ELT4(dq, j & 3) * NC2);
        N[m] = fmaf(w, N[m - 1], w * P[m - 1]);
    }
    N[33] = N[32] + P[32] + P[33];
}

// Row 0: E[m] = prod of w (cumsum in log space).
__device__ __forceinline__ void row0_step(const float* __restrict__ drow,
                                          float* __restrict__ N) {
    float4 dq = *reinterpret_cast<const float4*>(drow);
    N[1] = ex2f(dq.x * NC2) * TWO_S;
    #pragma unroll
    for (int m = 2; m <= 32; m++) {
        const int j = m - 1;
        if ((j & 3) == 0) dq = *reinterpret_cast<const float4*>(drow + j);
        N[m] = N[m - 1] * ex2f(ELT4(dq, j & 3) * NC2);
    }
    N[33] = N[32];
}

__global__ void __launch_bounds__(PPB)
otam_kernel(const float* __restrict__ dists, float* __restrict__ out) {
    extern __shared__ float smem[];
    const int lane = threadIdx.x & 31;
    const int wid  = threadIdx.x >> 5;
    const int pw   = blockIdx.x * PPB + wid * PPW;
    if (pw >= QTOT) return;     // whole-warp guard (last block: warps 2,3 idle)

    float* wsm = smem + wid * WARP_WORDS;
    const unsigned int wsm_u32 = (unsigned int)__cvta_generic_to_shared(wsm);

    // Stage s = rows {2s, 2s+1} of this warp's 32 problems (64 floats each),
    // coalesced 16B cp.asyncs into buffer (s & 1).
    auto prefetch = [&](int s) {
        const unsigned int bu = wsm_u32 + (unsigned int)((s & 1) * BUF_WORDS_1) * 4u;
        #pragma unroll
        for (int it = 0; it < 16; it++) {
            const int idx = it * 32 + lane;
            const int q = idx >> 4;          // local problem
            const int c = idx & 15;          // float4 within 2-row chunk
            const float* g = dists + (size_t)(pw + q) * 1024 + s * 64 + c * 4;
            cp_async16(bu + (unsigned int)(q * CHUNK_WORDS + c * 4) * 4u, g);
        }
        asm volatile("cp.async.commit_group;\n" ::);
    };

    float A[34], B[34];   // ping-pong row buffers (registers; static indices only)

    prefetch(0);
    prefetch(1);

    #pragma unroll 1
    for (int s = 0; s < 16; s++) {
        if (s < 15) { asm volatile("cp.async.wait_group 1;\n" ::); }
        else        { asm volatile("cp.async.wait_group 0;\n" ::); }
        __syncwarp();

        const float* ch = wsm + (s & 1) * BUF_WORDS_1 + lane * CHUNK_WORDS;

        // even row 2s: read B -> write A  (row 0: cumsum -> A)
        if (s == 0) row0_step(ch, A);
        else        row_step(ch, B, A);
        // odd row 2s+1: read A -> write B
        row_step(ch + 32, A, B);

        __syncwarp();                       // all lanes done with buffer (s&1)
        if (s + 2 < 16) prefetch(s + 2);    // refill the buffer just freed
    }

    // v = S - log2(E); out = v * lambda*ln2
    out[pw + lane] = fmaf(-LLN2, lg2f(B[33]), SLLN2);
}

extern "C" void kernel_launch(void* const* d_in, const int* in_sizes, int n_in,
                              void* d_out, int out_size) {
    const float* dists = (const float*)d_in[0];
    float* out = (float*)d_out;
    const int blocks = (QTOT + PPB - 1) / PPB;            // 313
    const size_t shmem = SMEM_WORDS * sizeof(float);      // 69632 B
    cudaFuncSetAttribute(otam_kernel, cudaFuncAttributeMaxDynamicSharedMemorySize,
                         (int)shmem);
    otam_kernel<<<blocks, PPB, shmem>>>(dists, out);
}

// round 9
// speedup vs baseline: 1.4723x; 1.1822x over previous
#include <cuda_runtime.h>
#include <cuda_bf16.h>
#include <cstdint>

// OTAM cumulative soft-min DP.  dists: [200,200,32,32] f32 -> out [200,200] f32.
// lambda = 0.5.
//
// Exp-domain cells inside skewed K-row strips:
//   E(l,m) = 2^(S - v(l,m)/(lambda*ln2)),  S = 96
//   interior: E = w * (left + diag),  w = 2^(-d*C2)   -> one FFMA on-chain
//   m==1:     E = w * (2^(S+1) + above)               (left=diag=2^S)
//   m==33:    E = left + diag + above                 (d=0 -> w=1)
//   row 0:    E[m] = E[m-1] * w_m,  E[33] = E[32]
//   out = lambda*ln2 * (S - log2(E(31,33)))
// K=4 rows in flight per thread (skew 1 column) -> 4 independent FFMA chains.
// Per-warp double-buffered 4-row cp.async stages (8 stages), coalesced 16B.

#define QTOT 40000
#define PPW 32                    // problems per warp
#define PPB 64                    // threads per block (2 warps)
#define CHUNK_WORDS 132           // 4 rows * 32 floats + 4 pad (528B, conflict-free)
#define BUF_WORDS_1 (PPW * CHUNK_WORDS)     // 4224 floats = 16896 B per buffer
#define WARP_WORDS (2 * BUF_WORDS_1)        // double buffered
#define SMEM_WORDS (2 * WARP_WORDS)         // 16896 floats = 67584 B per block

__device__ __forceinline__ float ex2f(float x) {
    float y; asm("ex2.approx.f32 %0, %1;" : "=f"(y) : "f"(x)); return y;
}
__device__ __forceinline__ float lg2f(float x) {
    float y; asm("lg2.approx.f32 %0, %1;" : "=f"(y) : "f"(x)); return y;
}
__device__ __forceinline__ void cp_async16(unsigned int dst, const void* src) {
    asm volatile("cp.async.cg.shared.global [%0], [%1], 16;\n"
                 :: "r"(dst), "l"(src) : "memory");
}

#define ELT4(v, k) ((k)==0 ? (v).x : ((k)==1 ? (v).y : ((k)==2 ? (v).z : (v).w)))

#define NC2    (-2.8853900817779268f)   // -1/(lambda*ln2)
#define LLN2   (0.34657359027997264f)   // lambda*ln2
#define TWO_S  (7.922816251426434e28f)  // 2^96
#define TWO_S2 (1.5845632502852868e29f) // 2^97
#define SLLN2  (33.271064666877374f)    // 96 * lambda*ln2

// K skewed rows in flight (row r one column ahead of row r+1), exp domain.
// rows[r*32 + j] = d(row r, col j) in this thread's smem chunk.
// prev[0..33] holds E of the row above the strip on entry (prev[0] = 2^S),
// and the strip's bottom row on exit.  Hazard: bottom row writes prev[m] at
// step m+K-1; row 0 last reads prev[m] at step m+1 -> K>=3 required.
template<int K>
__device__ __forceinline__ void run_strip(const float* __restrict__ rows, float* prev) {
    float cum[K], cumP[K];
    #pragma unroll
    for (int r = 0; r < K; r++) { cum[r] = TWO_S; cumP[r] = TWO_S; }

    float4 d4[K];

    #pragma unroll
    for (int t = 1; t <= 33 + K - 1; t++) {
        #pragma unroll
        for (int r = K - 1; r >= 0; r--) {
            const int m = t - r;
            if (m >= 1 && m <= 33) {
                const int j = m - 1;
                if (j < 32 && (j & 3) == 0)
                    d4[r] = *reinterpret_cast<const float4*>(rows + r * 32 + j);
                const float c = cum[r];                                 // left E
                float v;
                if (m == 1) {
                    const float pm = (r == 0) ? prev[1] : cum[r - 1];   // above
                    const float w  = ex2f(ELT4(d4[r], 0) * NC2);
                    v = w * (TWO_S2 + pm);
                } else if (m == 33) {
                    const float a  = (r == 0) ? prev[32] : cumP[r - 1]; // diag
                    const float pm = (r == 0) ? prev[33] : cum[r - 1];  // above
                    v = c + a + pm;                                     // w = 1
                } else {
                    const float a = (r == 0) ? prev[m - 1] : cumP[r - 1]; // diag
                    const float w = ex2f(ELT4(d4[r], j & 3) * NC2);
                    v = fmaf(w, c, w * a);
                }
                cumP[r] = c;
                cum[r]  = v;
                if (r == K - 1) prev[m] = v;
            }
        }
    }
}

__global__ void __launch_bounds__(PPB)
otam_kernel(const float* __restrict__ dists, float* __restrict__ out) {
    extern __shared__ float smem[];
    const int lane = threadIdx.x & 31;
    const int wid  = threadIdx.x >> 5;
    const int pw   = blockIdx.x * PPB + wid * PPW;   // 625*64 == 40000 exactly

    float* wsm = smem + wid * WARP_WORDS;            // this warp's region
    const unsigned int wsm_u32 = (unsigned int)__cvta_generic_to_shared(wsm);

    // Stage s = rows [4s .. 4s+3] of this warp's 32 problems (512B/problem),
    // coalesced 16B cp.asyncs into buffer (s & 1).
    auto prefetch = [&](int s) {
        const unsigned int bu = wsm_u32 + (unsigned int)((s & 1) * BUF_WORDS_1) * 4u;
        #pragma unroll
        for (int it = 0; it < 32; it++) {
            const int idx = it * 32 + lane;
            const int q = idx >> 5;          // local problem 0..31
            const int c = idx & 31;          // float4 within 4-row chunk
            const float* g = dists + (size_t)(pw + q) * 1024 + s * 128 + c * 4;
            cp_async16(bu + (unsigned int)(q * CHUNK_WORDS + c * 4) * 4u, g);
        }
        asm volatile("cp.async.commit_group;\n" ::);
    };

    float prev[34];

    prefetch(0);
    prefetch(1);

    #pragma unroll 1
    for (int s = 0; s < 8; s++) {
        if (s < 7) { asm volatile("cp.async.wait_group 1;\n" ::); }
        else       { asm volatile("cp.async.wait_group 0;\n" ::); }
        __syncwarp();

        const float* ch = wsm + (s & 1) * BUF_WORDS_1 + lane * CHUNK_WORDS;

        if (s == 0) {
            // row 0: E[m] = prod_{k<=m} 2^(-d_k*C2), anchored at 2^S
            float4 dq = *reinterpret_cast<const float4*>(ch);
            prev[0] = TWO_S;
            prev[1] = ex2f(dq.x * NC2) * TWO_S;
            #pragma unroll
            for (int m = 2; m <= 32; m++) {
                const int j = m - 1;
                if ((j & 3) == 0) dq = *reinterpret_cast<const float4*>(ch + j);
                prev[m] = prev[m - 1] * ex2f(ELT4(dq, j & 3) * NC2);
            }
            prev[33] = prev[32];
            run_strip<3>(ch + 32, prev);    // rows 1..3
        } else {
            run_strip<4>(ch, prev);         // rows 4s..4s+3
        }

        __syncwarp();                       // all lanes done with buffer (s&1)
        if (s + 2 < 8) prefetch(s + 2);     // refill the freed buffer
    }

    // v = S - log2(E); out = v * lambda*ln2
    out[pw + lane] = fmaf(-LLN2, lg2f(prev[33]), SLLN2);
}

extern "C" void kernel_launch(void* const* d_in, const int* in_sizes, int n_in,
                              void* d_out, int out_size) {
    const float* dists = (const float*)d_in[0];
    float* out = (float*)d_out;
    const int blocks = QTOT / PPB;                    // 625
    const size_t shmem = SMEM_WORDS * sizeof(float);  // 67584 B
    cudaFuncSetAttribute(otam_kernel, cudaFuncAttributeMaxDynamicSharedMemorySize,
                         (int)shmem);
    otam_kernel<<<blocks, PPB, shmem>>>(dists, out);
}